// round 17
// baseline (speedup 1.0000x reference)
#include <cuda_runtime.h>
#include <cuda_fp16.h>
#include <cstdint>
#include <cstddef>

#define TDIM 4096
#define HDIM 2048
#define FDIM 7168

// ---------------- GEMM configs ----------------
#define STG 4
#define FST 49152                     // fused stage: A 16KB | B1 16KB | B3 16KB
#define SMEMF (4 * FST)               // 196608
#define AST 16384
#define BST 32768
#define STB (AST + BST)
#define SMEMB (STG * STB)             // 196608

#define N4X (TDIM * HDIM / 4)

// ---------------- work queue layout (uber kernel) ----------------
#define GM12 (TDIM / 128)             // 32
#define GN12 (FDIM / 128)             // 56
#define NT12 (GM12 * GN12)            // 1792 tiles
#define NCVT_X  256                   // 32 blocks x 8 chunks (8192 float4 each)
#define NCVT_W  448                   // 56 blocks x 8 chunks (8192 float4 each)
#define NCVT_W2 512                   // 512 chunks (7168 float4 each)
#define CVT_X0  0
#define CVT_W10 (CVT_X0 + NCVT_X)     // 256
#define CVT_W30 (CVT_W10 + NCVT_W)    // 704
#define CVT_W20 (CVT_W30 + NCVT_W)    // 1152
#define NCVT    (CVT_W20 + NCVT_W2)   // 1664
#define NTOTAL  (NCVT + NT12)         // 3456

// ---------------- scratch (no allocations allowed) ----------------
__device__ __half d_xh[(size_t)TDIM * HDIM];
__device__ __half d_w1h[(size_t)FDIM * HDIM];
__device__ __half d_w3h[(size_t)FDIM * HDIM];
__device__ __half d_w2h[(size_t)HDIM * FDIM];
__device__ __half d_acth[(size_t)TDIM * FDIM];
__device__ int d_flag_x[GM12];        // counts to 8
__device__ int d_flag_w1[GN12];
__device__ int d_flag_w3[GN12];

// ---------------- helpers ----------------
__device__ __forceinline__ uint32_t smem_u32(const void* p) {
    uint32_t a;
    asm("{ .reg .u64 t; cvta.to.shared.u64 t, %1; cvt.u32.u64 %0, t; }" : "=r"(a) : "l"(p));
    return a;
}
__device__ __forceinline__ void cp_async16(uint32_t dst, const void* src) {
    asm volatile("cp.async.cg.shared.global [%0], [%1], 16;\n" :: "r"(dst), "l"(src));
}
__device__ __forceinline__ void cp_commit() { asm volatile("cp.async.commit_group;\n"); }
template <int N>
__device__ __forceinline__ void cp_wait() { asm volatile("cp.async.wait_group %0;\n" :: "n"(N)); }

__device__ __forceinline__ void ldm_x4(uint32_t* r, uint32_t addr) {
    asm volatile("ldmatrix.sync.aligned.m8n8.x4.shared.b16 {%0,%1,%2,%3}, [%4];"
                 : "=r"(r[0]), "=r"(r[1]), "=r"(r[2]), "=r"(r[3]) : "r"(addr));
}
__device__ __forceinline__ void mma_f16(float* d, const uint32_t* a, const uint32_t* b) {
    asm volatile(
        "mma.sync.aligned.m16n8k16.row.col.f32.f16.f16.f32 "
        "{%0,%1,%2,%3}, {%4,%5,%6,%7}, {%8,%9}, {%0,%1,%2,%3};\n"
        : "+f"(d[0]), "+f"(d[1]), "+f"(d[2]), "+f"(d[3])
        : "r"(a[0]), "r"(a[1]), "r"(a[2]), "r"(a[3]), "r"(b[0]), "r"(b[1]));
}
__device__ __forceinline__ float silu_f(float v) { return v / (1.0f + __expf(-v)); }

// coalesced fp32->fp16 of len4 float4 starting at base4 (256 threads)
__device__ __forceinline__ void cvt_range(const float4* __restrict__ src, uint2* __restrict__ dst,
                                          int base4, int len4, int tid) {
    for (int i = tid; i < len4; i += 256) {
        float4 v = src[base4 + i];
        __half2 h0 = __floats2half2_rn(v.x, v.y);
        __half2 h1 = __floats2half2_rn(v.z, v.w);
        dst[base4 + i] = make_uint2(*reinterpret_cast<uint32_t*>(&h0),
                                    *reinterpret_cast<uint32_t*>(&h1));
    }
}

__global__ void reset_flags_kernel() {
    int i = threadIdx.x;
    if (i < GM12) d_flag_x[i] = 0;
    if (i < GN12) { d_flag_w1[i] = 0; d_flag_w3[i] = 0; }
}

// ============ UBER kernel: [cvt chunks] ++ [fused g/u GEMM tiles], persistent ============
// act = silu(x@w1^T .* s1) * (x@w3^T .* s3), fp16 out. Mainloop byte-identical to R16.
// Queue: all cvt items precede all tiles -> each CTA finishes its cvt items before any
// of its tiles, and cvt items never wait -> deadlock-free. Tiles spin on block flags.
__global__ __launch_bounds__(256, 1)
void uber12(const float4* __restrict__ Xf, const float4* __restrict__ W1f,
            const float4* __restrict__ W3f, const float4* __restrict__ W2f,
            const __half* __restrict__ A,
            const __half* __restrict__ B1, const float* __restrict__ S1,
            const __half* __restrict__ B3, const float* __restrict__ S3,
            __half* __restrict__ Act,
            int M, int N, int K)
{
    extern __shared__ char smem[];
    const uint32_t sb = smem_u32(smem);
    const int tid = threadIdx.x;
    const int wid = tid >> 5, lane = tid & 31;
    const int wm = wid & 1, wn = wid >> 1;
    const int mat = lane >> 3, mr = lane & 7;
    const int g = lane >> 2, t4 = lane & 3;

    const int NP = K >> 7;

    for (int t = blockIdx.x; t < NTOTAL; t += gridDim.x) {
        if (t < NCVT) {
            // ---------- conversion work item ----------
            if (t < CVT_W10) {                    // x chunk
                int id = t - CVT_X0;
                int blk = id >> 3, c = id & 7;
                cvt_range(Xf, (uint2*)d_xh, blk * 65536 + c * 8192, 8192, tid);
                __threadfence();
                __syncthreads();
                if (tid == 0) atomicAdd(&d_flag_x[blk], 1);
            } else if (t < CVT_W30) {             // w1 chunk
                int id = t - CVT_W10;
                int blk = id >> 3, c = id & 7;
                cvt_range(W1f, (uint2*)d_w1h, blk * 65536 + c * 8192, 8192, tid);
                __threadfence();
                __syncthreads();
                if (tid == 0) atomicAdd(&d_flag_w1[blk], 1);
            } else if (t < CVT_W20) {             // w3 chunk
                int id = t - CVT_W30;
                int blk = id >> 3, c = id & 7;
                cvt_range(W3f, (uint2*)d_w3h, blk * 65536 + c * 8192, 8192, tid);
                __threadfence();
                __syncthreads();
                if (tid == 0) atomicAdd(&d_flag_w3[blk], 1);
            } else {                              // w2 chunk (no flag: used next launch)
                int id = t - CVT_W20;
                cvt_range(W2f, (uint2*)d_w2h, id * 7168, 7168, tid);
            }
            continue;
        }

        // ---------- fused g/u GEMM tile ----------
        const int tt0 = t - NCVT;
        const int bn = tt0 / GM12;
        const int bm = tt0 - bn * GM12;

        // wait for the input blocks this tile needs
        if (tid == 0) {
            while (atomicAdd(&d_flag_x[bm], 0) < 8) { }
            while (atomicAdd(&d_flag_w1[bn], 0) < 8) { }
            while (atomicAdd(&d_flag_w3[bn], 0) < 8) { }
            __threadfence();
        }
        __syncthreads();

        const __half* Ab  = A  + (size_t)bm * 128 * K;
        const __half* B1b = B1 + (size_t)bn * 128 * K;
        const __half* B3b = B3 + (size_t)bn * 128 * K;
        const float* Srow1 = S1 + (size_t)bn * NP;
        const float* Srow3 = S3 + (size_t)bn * NP;

        auto load_pair = [&](int p) {
            #pragma unroll
            for (int h = 0; h < 2; h++) {
                const uint32_t base = sb + ((p & 1) * 2 + h) * FST;
                const int k0 = (p << 7) + (h << 6);
                #pragma unroll
                for (int q = 0; q < 4; q++) {
                    int idx = tid + q * 256;
                    int row = idx >> 3, c = idx & 7;
                    uint32_t off = (uint32_t)(row << 7) + (c << 4);
                    uint32_t sw = off ^ ((off >> 3) & 0x70);
                    cp_async16(base + sw, Ab + (size_t)row * K + k0 + c * 8);
                }
                #pragma unroll
                for (int q = 0; q < 4; q++) {
                    int idx = tid + q * 256;
                    int row = idx >> 3, c = idx & 7;
                    uint32_t off = (uint32_t)(row << 7) + (c << 4);
                    uint32_t sw = off ^ ((off >> 3) & 0x70);
                    cp_async16(base + 16384 + sw, B1b + (size_t)row * K + k0 + c * 8);
                }
                #pragma unroll
                for (int q = 0; q < 4; q++) {
                    int idx = tid + q * 256;
                    int row = idx >> 3, c = idx & 7;
                    uint32_t off = (uint32_t)(row << 7) + (c << 4);
                    uint32_t sw = off ^ ((off >> 3) & 0x70);
                    cp_async16(base + 32768 + sw, B3b + (size_t)row * K + k0 + c * 8);
                }
            }
            cp_commit();
        };

        float accg[4][4][4], accu[4][4][4];
        #pragma unroll
        for (int mt = 0; mt < 4; mt++)
            #pragma unroll
            for (int nt = 0; nt < 4; nt++)
                #pragma unroll
                for (int i = 0; i < 4; i++) { accg[mt][nt][i] = 0.0f; accu[mt][nt][i] = 0.0f; }

        load_pair(0);
        float s1_cur = __ldg(Srow1);
        float s3_cur = __ldg(Srow3);

        for (int p = 0; p < NP; p++) {
            float rr1 = 1.0f, rr3 = 1.0f;
            if (p) {
                float sn1 = __ldg(Srow1 + p);
                float sn3 = __ldg(Srow3 + p);
                rr1 = s1_cur / sn1; s1_cur = sn1;
                rr3 = s3_cur / sn3; s3_cur = sn3;
            }

            cp_wait<0>();
            __syncthreads();

            if (p + 1 < NP) load_pair(p + 1);

            #pragma unroll
            for (int h = 0; h < 2; h++) {
                const uint32_t base = sb + ((p & 1) * 2 + h) * FST;
                #pragma unroll
                for (int ks = 0; ks < 4; ks++) {
                    uint32_t af[4][4], bf1[2][4], bf3[2][4];
                    #pragma unroll
                    for (int mt = 0; mt < 4; mt++) {
                        int row = wm * 64 + mt * 16 + (mat & 1) * 8 + mr;
                        uint32_t off = (uint32_t)(row << 7) + ks * 32 + (mat >> 1) * 16;
                        uint32_t sw = off ^ ((off >> 3) & 0x70);
                        ldm_x4(af[mt], base + sw);
                    }
                    #pragma unroll
                    for (int bq = 0; bq < 2; bq++) {
                        int nrow = wn * 32 + (bq * 2 + (mat >> 1)) * 8 + mr;
                        uint32_t off = (uint32_t)(nrow << 7) + ks * 32 + (mat & 1) * 16;
                        uint32_t sw = off ^ ((off >> 3) & 0x70);
                        ldm_x4(bf1[bq], base + 16384 + sw);
                        ldm_x4(bf3[bq], base + 32768 + sw);
                    }
                    if (h == 0 && ks == 0) {
                        #pragma unroll
                        for (int mt = 0; mt < 4; mt++)
                            #pragma unroll
                            for (int nt = 0; nt < 4; nt++) {
                                accg[mt][nt][0] *= rr1; accg[mt][nt][1] *= rr1;
                                accg[mt][nt][2] *= rr1; accg[mt][nt][3] *= rr1;
                                mma_f16(accg[mt][nt], af[mt], &bf1[nt >> 1][(nt & 1) * 2]);
                                accu[mt][nt][0] *= rr3; accu[mt][nt][1] *= rr3;
                                accu[mt][nt][2] *= rr3; accu[mt][nt][3] *= rr3;
                                mma_f16(accu[mt][nt], af[mt], &bf3[nt >> 1][(nt & 1) * 2]);
                            }
                    } else {
                        #pragma unroll
                        for (int mt = 0; mt < 4; mt++)
                            #pragma unroll
                            for (int nt = 0; nt < 4; nt++) {
                                mma_f16(accg[mt][nt], af[mt], &bf1[nt >> 1][(nt & 1) * 2]);
                                mma_f16(accu[mt][nt], af[mt], &bf3[nt >> 1][(nt & 1) * 2]);
                            }
                    }
                }
            }
        }

        #pragma unroll
        for (int mt = 0; mt < 4; mt++) {
            int r0 = bm * 128 + wm * 64 + mt * 16 + g;
            #pragma unroll
            for (int nt = 0; nt < 4; nt++) {
                int c0 = bn * 128 + wn * 32 + nt * 8 + t4 * 2;
                float g0 = accg[mt][nt][0] * s1_cur, g1 = accg[mt][nt][1] * s1_cur;
                float g2 = accg[mt][nt][2] * s1_cur, g3 = accg[mt][nt][3] * s1_cur;
                float u0 = accu[mt][nt][0] * s3_cur, u1 = accu[mt][nt][1] * s3_cur;
                float u2 = accu[mt][nt][2] * s3_cur, u3 = accu[mt][nt][3] * s3_cur;
                __half2 h0 = __floats2half2_rn(silu_f(g0) * u0, silu_f(g1) * u1);
                __half2 h1 = __floats2half2_rn(silu_f(g2) * u2, silu_f(g3) * u3);
                *reinterpret_cast<__half2*>(&Act[(size_t)r0 * N + c0]) = h0;
                *reinterpret_cast<__half2*>(&Act[(size_t)(r0 + 8) * N + c0]) = h1;
            }
        }
        __syncthreads();   // all threads done with this tile before next queue item
    }
}

// ============ GEMM3: R14/R16-validated persistent 128x256 kernel ============
__global__ __launch_bounds__(256, 1)
void gemm_f16(const __half* __restrict__ A,
              const __half* __restrict__ B0, const float* __restrict__ S0, void* __restrict__ C0,
              int M, int N, int K, int out_half)
{
    extern __shared__ char smem[];
    const uint32_t sb = smem_u32(smem);
    const int tid = threadIdx.x;
    const int wid = tid >> 5, lane = tid & 31;
    const int wm = wid & 1, wn = wid >> 1;
    const int mat = lane >> 3, mr = lane & 7;
    const int g = lane >> 2, t4 = lane & 3;

    const int GM = M >> 7;
    const int GN = N >> 8;
    const int NP = K >> 7;
    const int total = GM * GN;

    for (int t = blockIdx.x; t < total; t += gridDim.x) {
        const int bn = t / GM;
        const int bm = t - bn * GM;

        const __half* Ab = A + (size_t)bm * 128 * K;
        const __half* Bb = B0 + (size_t)bn * 256 * K;
        const float* Srow = S0 + (size_t)(bn * 2 + (wn >> 1)) * NP;

        auto load_pair = [&](int p) {
            #pragma unroll
            for (int h = 0; h < 2; h++) {
                const uint32_t ab = sb + ((p & 1) * 2 + h) * STB;
                const uint32_t bb = ab + AST;
                const int k0 = (p << 7) + (h << 6);
                #pragma unroll
                for (int q = 0; q < 4; q++) {
                    int idx = tid + q * 256;
                    int row = idx >> 3, c = idx & 7;
                    uint32_t off = (uint32_t)(row << 7) + (c << 4);
                    uint32_t sw = off ^ ((off >> 3) & 0x70);
                    cp_async16(ab + sw, Ab + (size_t)row * K + k0 + c * 8);
                }
                #pragma unroll
                for (int q = 0; q < 8; q++) {
                    int idx = tid + q * 256;
                    int row = idx >> 3, c = idx & 7;
                    uint32_t off = (uint32_t)(row << 7) + (c << 4);
                    uint32_t sw = off ^ ((off >> 3) & 0x70);
                    cp_async16(bb + sw, Bb + (size_t)row * K + k0 + c * 8);
                }
            }
            cp_commit();
        };

        float acc[4][8][4];
        #pragma unroll
        for (int mt = 0; mt < 4; mt++)
            #pragma unroll
            for (int nt = 0; nt < 8; nt++)
                #pragma unroll
                for (int i = 0; i < 4; i++) acc[mt][nt][i] = 0.0f;

        load_pair(0);
        float s_cur = __ldg(Srow);

        for (int p = 0; p < NP; p++) {
            float rr = 1.0f;
            if (p) {
                float sn = __ldg(Srow + p);
                rr = s_cur / sn;
                s_cur = sn;
            }

            cp_wait<0>();
            __syncthreads();

            if (p + 1 < NP) load_pair(p + 1);

            #pragma unroll
            for (int h = 0; h < 2; h++) {
                const uint32_t ab = sb + ((p & 1) * 2 + h) * STB;
                const uint32_t bb = ab + AST;
                #pragma unroll
                for (int ks = 0; ks < 4; ks++) {
                    uint32_t af[4][4], bf[4][4];
                    #pragma unroll
                    for (int mt = 0; mt < 4; mt++) {
                        int row = wm * 64 + mt * 16 + (mat & 1) * 8 + mr;
                        uint32_t off = (uint32_t)(row << 7) + ks * 32 + (mat >> 1) * 16;
                        uint32_t sw = off ^ ((off >> 3) & 0x70);
                        ldm_x4(af[mt], ab + sw);
                    }
                    #pragma unroll
                    for (int bq = 0; bq < 4; bq++) {
                        int nrow = wn * 64 + (bq * 2 + (mat >> 1)) * 8 + mr;
                        uint32_t off = (uint32_t)(nrow << 7) + ks * 32 + (mat & 1) * 16;
                        uint32_t sw = off ^ ((off >> 3) & 0x70);
                        ldm_x4(bf[bq], bb + sw);
                    }
                    if (h == 0 && ks == 0) {
                        #pragma unroll
                        for (int mt = 0; mt < 4; mt++)
                            #pragma unroll
                            for (int nt = 0; nt < 8; nt++) {
                                acc[mt][nt][0] *= rr;
                                acc[mt][nt][1] *= rr;
                                acc[mt][nt][2] *= rr;
                                acc[mt][nt][3] *= rr;
                                mma_f16(acc[mt][nt], af[mt], &bf[nt >> 1][(nt & 1) * 2]);
                            }
                    } else {
                        #pragma unroll
                        for (int mt = 0; mt < 4; mt++)
                            #pragma unroll
                            for (int nt = 0; nt < 8; nt++)
                                mma_f16(acc[mt][nt], af[mt], &bf[nt >> 1][(nt & 1) * 2]);
                    }
                }
            }
        }

        if (out_half) {
            __half* Ch = (__half*)C0;
            #pragma unroll
            for (int mt = 0; mt < 4; mt++) {
                int r0 = bm * 128 + wm * 64 + mt * 16 + g;
                #pragma unroll
                for (int nt = 0; nt < 8; nt++) {
                    int c0 = bn * 256 + wn * 64 + nt * 8 + t4 * 2;
                    __half2 h0 = __floats2half2_rn(acc[mt][nt][0] * s_cur, acc[mt][nt][1] * s_cur);
                    __half2 h1 = __floats2half2_rn(acc[mt][nt][2] * s_cur, acc[mt][nt][3] * s_cur);
                    *reinterpret_cast<__half2*>(&Ch[(size_t)r0 * N + c0]) = h0;
                    *reinterpret_cast<__half2*>(&Ch[(size_t)(r0 + 8) * N + c0]) = h1;
                }
            }
        } else {
            float* Cf = (float*)C0;
            #pragma unroll
            for (int mt = 0; mt < 4; mt++) {
                int r0 = bm * 128 + wm * 64 + mt * 16 + g;
                #pragma unroll
                for (int nt = 0; nt < 8; nt++) {
                    int c0 = bn * 256 + wn * 64 + nt * 8 + t4 * 2;
                    float2 v0 = make_float2(acc[mt][nt][0] * s_cur, acc[mt][nt][1] * s_cur);
                    float2 v1 = make_float2(acc[mt][nt][2] * s_cur, acc[mt][nt][3] * s_cur);
                    *reinterpret_cast<float2*>(&Cf[(size_t)r0 * N + c0]) = v0;
                    *reinterpret_cast<float2*>(&Cf[(size_t)(r0 + 8) * N + c0]) = v1;
                }
            }
        }
    }
}

// ---------------- launch ----------------
extern "C" void kernel_launch(void* const* d_in, const int* in_sizes, int n_in,
                              void* d_out, int out_size) {
    (void)in_sizes; (void)n_in; (void)out_size;
    const float* x   = (const float*)d_in[0];
    const float* w1q = (const float*)d_in[1];
    const float* w1s = (const float*)d_in[2];
    const float* w3q = (const float*)d_in[3];
    const float* w3s = (const float*)d_in[4];
    const float* w2q = (const float*)d_in[5];
    const float* w2s = (const float*)d_in[6];
    float* out = (float*)d_out;

    __half *xh, *w1h, *w3h, *w2h, *acth;
    cudaGetSymbolAddress((void**)&xh,   d_xh);
    cudaGetSymbolAddress((void**)&w1h,  d_w1h);
    cudaGetSymbolAddress((void**)&w3h,  d_w3h);
    cudaGetSymbolAddress((void**)&w2h,  d_w2h);
    cudaGetSymbolAddress((void**)&acth, d_acth);

    int nsm = 148;
    cudaDeviceGetAttribute(&nsm, cudaDevAttrMultiProcessorCount, 0);

    cudaFuncSetAttribute(uber12, cudaFuncAttributeMaxDynamicSharedMemorySize, SMEMF);
    cudaFuncSetAttribute(gemm_f16, cudaFuncAttributeMaxDynamicSharedMemorySize, SMEMB);

    // reset publish flags (graph replays re-run this)
    reset_flags_kernel<<<1, 64>>>();

    // uber: conversions (x,w1,w3,w2) + fused act GEMM in one persistent launch.
    // grid <= SM count guarantees co-residency for the flag/spin protocol.
    uber12<<<nsm, 256, SMEMF>>>(
        (const float4*)x, (const float4*)w1q, (const float4*)w3q, (const float4*)w2q,
        xh, w1h, w1s, w3h, w3s, acth, TDIM, FDIM, HDIM);

    // out = act @ w2^T  (fp32 out, persistent)
    {
        const int tiles = (TDIM / 128) * (HDIM / 256);
        const int grid = tiles < nsm ? tiles : nsm;
        gemm_f16<<<grid, 256, SMEMB>>>(acth, w2h, w2s, out, TDIM, HDIM, FDIM, 0);
    }
}